// round 5
// baseline (speedup 1.0000x reference)
#include <cuda_runtime.h>
#include <cuda_bf16.h>

#define N_NODES 100000
#define N_EDGES 600000
#define N_GRAPHS 2000
#define HID 128
#define LAYERS 6

// Scratch buffers (allocation-free rule: __device__ globals)
__device__ float g_x[(size_t)N_NODES * HID];
__device__ float g_agg[(size_t)N_NODES * HID];
__device__ float g_h[(size_t)N_NODES * HID];
__device__ float g_cnt[N_GRAPHS];

// ---------------------------------------------------------------------------
// Embedding gather: x[node] = emb[tok[node]]
// ---------------------------------------------------------------------------
__global__ void embed_kernel(const int* __restrict__ tok,
                             const float* __restrict__ emb,
                             float* __restrict__ x) {
    int i = blockIdx.x * blockDim.x + threadIdx.x;   // over N_NODES*32 float4
    if (i >= N_NODES * 32) return;
    int node = i >> 5;
    int c    = i & 31;
    int t = __ldg(tok + node);
    ((float4*)x)[(size_t)node * 32 + c] =
        ((const float4*)emb)[(size_t)t * 32 + c];
}

// ---------------------------------------------------------------------------
// Generic float4 zero
// ---------------------------------------------------------------------------
__global__ void zero_kernel(float4* __restrict__ p, int n4) {
    int i = blockIdx.x * blockDim.x + threadIdx.x;
    if (i < n4) p[i] = make_float4(0.f, 0.f, 0.f, 0.f);
}

// ---------------------------------------------------------------------------
// Edge scatter: agg[dst] += x[src]  (one warp per edge, vector RED)
// ---------------------------------------------------------------------------
__global__ void scatter_kernel(const float* __restrict__ x,
                               const int* __restrict__ src,
                               const int* __restrict__ dst,
                               float* __restrict__ agg) {
    int w = (blockIdx.x * blockDim.x + threadIdx.x) >> 5;
    if (w >= N_EDGES) return;
    int lane = threadIdx.x & 31;
    int s = __ldg(src + w);
    int d = __ldg(dst + w);
    float4 v = ((const float4*)x)[(size_t)s * 32 + lane];
    float* p = agg + (size_t)d * HID + lane * 4;
    asm volatile("red.global.add.v4.f32 [%0], {%1, %2, %3, %4};"
                 :: "l"(p), "f"(v.x), "f"(v.y), "f"(v.z), "f"(v.w)
                 : "memory");
}

// ---------------------------------------------------------------------------
// Fused GEMM: C = relu((A [+ A2]) @ W + b)
//   A: [N_NODES, 128], W: [128,128] row-major (k,n), b: [128]
// Block: 256 threads, BM=64 rows, full K=N=128.
// Dynamic smem: sW 64KB + sA 32KB = 96KB.
// Each thread: 8 rows x 4 cols micro-tile.
// ---------------------------------------------------------------------------
__global__ void gemm_kernel(const float* __restrict__ A,
                            const float* __restrict__ A2,
                            const float* __restrict__ W,
                            const float* __restrict__ bias,
                            float* __restrict__ C) {
    extern __shared__ float sm[];
    float* sW = sm;              // [128][128]
    float* sA = sm + 128 * 128;  // [64][128]

    int tid  = threadIdx.x;
    int row0 = blockIdx.x * 64;

    // Load W tile (16384 floats = 4096 float4)
    for (int i = tid; i < 4096; i += 256)
        ((float4*)sW)[i] = ((const float4*)W)[i];

    // Load A tile (+optional A2) (64x128 = 2048 float4)
    for (int i = tid; i < 2048; i += 256) {
        int r = i >> 5, c = i & 31;
        int grow = row0 + r;
        float4 v = make_float4(0.f, 0.f, 0.f, 0.f);
        if (grow < N_NODES) {
            v = ((const float4*)A)[(size_t)grow * 32 + c];
            if (A2) {
                float4 u = ((const float4*)A2)[(size_t)grow * 32 + c];
                v.x += u.x; v.y += u.y; v.z += u.z; v.w += u.w;
            }
        }
        ((float4*)sA)[i] = v;
    }
    __syncthreads();

    int tx = tid & 31;   // column group (4 cols)
    int ty = tid >> 5;   // row group (8 rows)

    float acc[8][4];
#pragma unroll
    for (int i = 0; i < 8; i++)
#pragma unroll
        for (int j = 0; j < 4; j++) acc[i][j] = 0.f;

#pragma unroll 4
    for (int k4 = 0; k4 < 32; k4++) {
        float4 a[8];
#pragma unroll
        for (int i = 0; i < 8; i++)
            a[i] = ((const float4*)(sA + (ty * 8 + i) * 128))[k4];   // broadcast
#pragma unroll
        for (int kk = 0; kk < 4; kk++) {
            float4 w = ((const float4*)(sW + (k4 * 4 + kk) * 128))[tx];
#pragma unroll
            for (int i = 0; i < 8; i++) {
                float av = (kk == 0) ? a[i].x : (kk == 1) ? a[i].y
                          : (kk == 2) ? a[i].z : a[i].w;
                acc[i][0] += av * w.x;
                acc[i][1] += av * w.y;
                acc[i][2] += av * w.z;
                acc[i][3] += av * w.w;
            }
        }
    }

    float4 b4 = ((const float4*)bias)[tx];
#pragma unroll
    for (int i = 0; i < 8; i++) {
        int grow = row0 + ty * 8 + i;
        if (grow < N_NODES) {
            float4 v;
            v.x = fmaxf(acc[i][0] + b4.x, 0.f);
            v.y = fmaxf(acc[i][1] + b4.y, 0.f);
            v.z = fmaxf(acc[i][2] + b4.z, 0.f);
            v.w = fmaxf(acc[i][3] + b4.w, 0.f);
            ((float4*)C)[(size_t)grow * 32 + tx] = v;
        }
    }
}

// ---------------------------------------------------------------------------
// Global mean pool: out[g] = mean over nodes with batch==g
// ---------------------------------------------------------------------------
__global__ void pool_kernel(const float* __restrict__ x,
                            const int* __restrict__ batch,
                            float* __restrict__ out) {
    int w = (blockIdx.x * blockDim.x + threadIdx.x) >> 5;
    if (w >= N_NODES) return;
    int lane = threadIdx.x & 31;
    int g = __ldg(batch + w);
    float4 v = ((const float4*)x)[(size_t)w * 32 + lane];
    float* p = out + (size_t)g * HID + lane * 4;
    asm volatile("red.global.add.v4.f32 [%0], {%1, %2, %3, %4};"
                 :: "l"(p), "f"(v.x), "f"(v.y), "f"(v.z), "f"(v.w)
                 : "memory");
    if (lane == 0) atomicAdd(&g_cnt[g], 1.0f);
}

__global__ void div_kernel(float* __restrict__ out) {
    int i = blockIdx.x * blockDim.x + threadIdx.x;   // N_GRAPHS*32 float4
    if (i >= N_GRAPHS * 32) return;
    int g = i >> 5;
    float c = fmaxf(g_cnt[g], 1.0f);
    float inv = 1.0f / c;
    float4 v = ((float4*)out)[i];
    v.x *= inv; v.y *= inv; v.z *= inv; v.w *= inv;
    ((float4*)out)[i] = v;
}

// ---------------------------------------------------------------------------
extern "C" void kernel_launch(void* const* d_in, const int* in_sizes, int n_in,
                              void* d_out, int out_size) {
    const int*   tok   = (const int*)d_in[0];
    const int*   ei    = (const int*)d_in[1];   // [2, N_EDGES]
    const int*   batch = (const int*)d_in[2];
    const float* emb   = (const float*)d_in[3];
    const float* W1    = (const float*)d_in[4];
    const float* b1    = (const float*)d_in[5];
    const float* W2    = (const float*)d_in[6];
    const float* b2    = (const float*)d_in[7];
    float* out = (float*)d_out;

    cudaFuncSetAttribute(gemm_kernel,
                         cudaFuncAttributeMaxDynamicSharedMemorySize, 98304);

    float *x, *agg, *h, *cnt;
    cudaGetSymbolAddress((void**)&x,   g_x);
    cudaGetSymbolAddress((void**)&agg, g_agg);
    cudaGetSymbolAddress((void**)&h,   g_h);
    cudaGetSymbolAddress((void**)&cnt, g_cnt);

    const int* src = ei;
    const int* dst = ei + N_EDGES;

    // Embedding lookup
    embed_kernel<<<(N_NODES * 32 + 255) / 256, 256>>>(tok, emb, x);

    int gemm_grid = (N_NODES + 63) / 64;

    for (int l = 0; l < LAYERS; l++) {
        zero_kernel<<<(N_NODES * 32 + 255) / 256, 256>>>((float4*)agg, N_NODES * 32);
        scatter_kernel<<<(N_EDGES * 32 + 255) / 256, 256>>>(x, src, dst, agg);
        // h = relu((x + agg) @ W1[l] + b1[l])
        gemm_kernel<<<gemm_grid, 256, 98304>>>(x, agg,
                                               W1 + (size_t)l * HID * HID,
                                               b1 + (size_t)l * HID, h);
        // x = relu(h @ W2[l] + b2[l])
        gemm_kernel<<<gemm_grid, 256, 98304>>>(h, nullptr,
                                               W2 + (size_t)l * HID * HID,
                                               b2 + (size_t)l * HID, x);
    }

    // Mean pool
    zero_kernel<<<(N_GRAPHS * 32 + 255) / 256, 256>>>((float4*)out, N_GRAPHS * 32);
    zero_kernel<<<(N_GRAPHS / 4 + 255) / 256, 256>>>((float4*)cnt, N_GRAPHS / 4);
    pool_kernel<<<(N_NODES * 32 + 255) / 256, 256>>>(x, batch, out);
    div_kernel<<<(N_GRAPHS * 32 + 255) / 256, 256>>>(out);
}

// round 8
// speedup vs baseline: 1.0380x; 1.0380x over previous
#include <cuda_runtime.h>
#include <cuda_bf16.h>
#include <cstdint>

#define N_NODES 100000
#define N_EDGES 600000
#define N_GRAPHS 2000
#define HID 128
#define LAYERS 6

// Scratch buffers (allocation-free rule: __device__ globals)
__device__ float g_x[(size_t)N_NODES * HID];
__device__ float g_agg[(size_t)N_NODES * HID];
__device__ float g_h[(size_t)N_NODES * HID];
__device__ float g_cnt[N_GRAPHS];

// Packed f32x2 helpers (plain sm_100-family PTX, not 'a'-gated)
#define FMA_F32X2(acc, a, b) \
    asm("fma.rn.f32x2 %0, %1, %2, %0;" : "+l"(acc) : "l"(a), "l"(b))
#define PACK_DUP(d, s) \
    asm("mov.b64 %0, {%1, %1};" : "=l"(d) : "f"(s))
#define UNPACK2(lo, hi, v) \
    asm("mov.b64 {%0, %1}, %2;" : "=f"(lo), "=f"(hi) : "l"(v))

// ---------------------------------------------------------------------------
// Embedding gather: x[node] = emb[tok[node]]
// ---------------------------------------------------------------------------
__global__ void embed_kernel(const int* __restrict__ tok,
                             const float* __restrict__ emb,
                             float* __restrict__ x) {
    int i = blockIdx.x * blockDim.x + threadIdx.x;
    if (i >= N_NODES * 32) return;
    int node = i >> 5;
    int c    = i & 31;
    int t = __ldg(tok + node);
    ((float4*)x)[(size_t)node * 32 + c] =
        ((const float4*)emb)[(size_t)t * 32 + c];
}

__global__ void zero_kernel(float4* __restrict__ p, int n4) {
    int i = blockIdx.x * blockDim.x + threadIdx.x;
    if (i < n4) p[i] = make_float4(0.f, 0.f, 0.f, 0.f);
}

// ---------------------------------------------------------------------------
// Edge scatter: agg[dst] += x[src]  (one warp per edge, vector RED)
// ---------------------------------------------------------------------------
__global__ void scatter_kernel(const float* __restrict__ x,
                               const int* __restrict__ src,
                               const int* __restrict__ dst,
                               float* __restrict__ agg) {
    int w = (blockIdx.x * blockDim.x + threadIdx.x) >> 5;
    if (w >= N_EDGES) return;
    int lane = threadIdx.x & 31;
    int s = __ldg(src + w);
    int d = __ldg(dst + w);
    float4 v = ((const float4*)x)[(size_t)s * 32 + lane];
    float* p = agg + (size_t)d * HID + lane * 4;
    asm volatile("red.global.add.v4.f32 [%0], {%1, %2, %3, %4};"
                 :: "l"(p), "f"(v.x), "f"(v.y), "f"(v.z), "f"(v.w)
                 : "memory");
}

// ---------------------------------------------------------------------------
// FFMA2 GEMM: C = relu((A [+ A2]) @ W + b)
//   A: [N_NODES,128], W: [128,128] (k,n) row-major, b: [128]
// CTA: 256 threads (8 warps), tile M=128 rows, N=128 cols.
//   warp w -> rows w*16..w*16+15 ; lane -> cols lane*4..lane*4+3
//   acc[p][c] = f32x2 pair of rows (2p, 2p+1) at col c  (32 u64 regs)
// sA is k-major transposed [k][row] (stride 132 floats) so one LDS.128
// yields 4 consecutive rows = 2 f32x2 pairs, broadcast across the warp.
// K processed in 2 chunks of 64. SMEM = 64KB (W) + 33KB (A) -> 2 CTAs/SM.
// ---------------------------------------------------------------------------
#define SA_STRIDE 132

__global__ __launch_bounds__(256, 2) void gemm_kernel(
    const float* __restrict__ A, const float* __restrict__ A2,
    const float* __restrict__ W, const float* __restrict__ bias,
    float* __restrict__ C) {
    extern __shared__ float sm[];
    float* sW = sm;                  // [128][128]
    float* sA = sm + 128 * 128;      // [64][SA_STRIDE]

    int tid  = threadIdx.x;
    int wid  = tid >> 5;
    int lane = tid & 31;
    int row0 = blockIdx.x * 128;

    // Load full W tile (16384 floats = 4096 float4), coalesced
    for (int i = tid; i < 4096; i += 256)
        ((float4*)sW)[i] = ((const float4*)W)[i];

    unsigned long long acc[8][4];
#pragma unroll
    for (int p = 0; p < 8; p++)
#pragma unroll
        for (int c = 0; c < 4; c++) acc[p][c] = 0ull;

    for (int ck = 0; ck < 2; ck++) {
        __syncthreads();   // sW ready (ck=0) / previous chunk compute done (ck=1)
        // Load A chunk transposed: sA[k][r] for k in [0,64), r in [0,128)
        // lane -> row mapping keeps the 4 scalar STS conflict-free.
#pragma unroll
        for (int it = 0; it < 8; it++) {
            int i  = tid + it * 256;     // 0..2047
            int c4 = i >> 7;             // 0..15  (float4 within chunk)
            int r  = i & 127;            // row in tile
            int row = row0 + r;
            float4 v = make_float4(0.f, 0.f, 0.f, 0.f);
            if (row < N_NODES) {
                v = ((const float4*)A)[(size_t)row * 32 + ck * 16 + c4];
                if (A2) {
                    float4 u = ((const float4*)A2)[(size_t)row * 32 + ck * 16 + c4];
                    v.x += u.x; v.y += u.y; v.z += u.z; v.w += u.w;
                }
            }
            sA[(c4 * 4 + 0) * SA_STRIDE + r] = v.x;
            sA[(c4 * 4 + 1) * SA_STRIDE + r] = v.y;
            sA[(c4 * 4 + 2) * SA_STRIDE + r] = v.z;
            sA[(c4 * 4 + 3) * SA_STRIDE + r] = v.w;
        }
        __syncthreads();

#pragma unroll 4
        for (int k = 0; k < 64; k++) {
            // A: 16 rows for this warp = 4 broadcast LDS.128 = 8 f32x2 pairs
            const ulonglong2* ap =
                (const ulonglong2*)(sA + k * SA_STRIDE + wid * 16);
            ulonglong2 av0 = ap[0], av1 = ap[1], av2 = ap[2], av3 = ap[3];
            unsigned long long apair[8] = {av0.x, av0.y, av1.x, av1.y,
                                           av2.x, av2.y, av3.x, av3.y};
            // W: 4 cols for this lane, duplicated into f32x2
            float4 w4 = *(const float4*)(sW + (ck * 64 + k) * 128 + lane * 4);
            unsigned long long wp[4];
            PACK_DUP(wp[0], w4.x);
            PACK_DUP(wp[1], w4.y);
            PACK_DUP(wp[2], w4.z);
            PACK_DUP(wp[3], w4.w);
#pragma unroll
            for (int p = 0; p < 8; p++) {
#pragma unroll
                for (int c = 0; c < 4; c++)
                    FMA_F32X2(acc[p][c], apair[p], wp[c]);
            }
        }
    }

    // Epilogue: bias + relu, coalesced float4 stores (warp-uniform rows)
    float4 b4 = ((const float4*)bias)[lane];
#pragma unroll
    for (int p = 0; p < 8; p++) {
        float lo[4], hi[4];
#pragma unroll
        for (int c = 0; c < 4; c++) UNPACK2(lo[c], hi[c], acc[p][c]);
        int rg = row0 + wid * 16 + 2 * p;
        if (rg < N_NODES) {
            float4 o;
            o.x = fmaxf(lo[0] + b4.x, 0.f);
            o.y = fmaxf(lo[1] + b4.y, 0.f);
            o.z = fmaxf(lo[2] + b4.z, 0.f);
            o.w = fmaxf(lo[3] + b4.w, 0.f);
            ((float4*)C)[(size_t)rg * 32 + lane] = o;
        }
        if (rg + 1 < N_NODES) {
            float4 o;
            o.x = fmaxf(hi[0] + b4.x, 0.f);
            o.y = fmaxf(hi[1] + b4.y, 0.f);
            o.z = fmaxf(hi[2] + b4.z, 0.f);
            o.w = fmaxf(hi[3] + b4.w, 0.f);
            ((float4*)C)[(size_t)(rg + 1) * 32 + lane] = o;
        }
    }
}

// ---------------------------------------------------------------------------
// Global mean pool
// ---------------------------------------------------------------------------
__global__ void pool_kernel(const float* __restrict__ x,
                            const int* __restrict__ batch,
                            float* __restrict__ out) {
    int w = (blockIdx.x * blockDim.x + threadIdx.x) >> 5;
    if (w >= N_NODES) return;
    int lane = threadIdx.x & 31;
    int g = __ldg(batch + w);
    float4 v = ((const float4*)x)[(size_t)w * 32 + lane];
    float* p = out + (size_t)g * HID + lane * 4;
    asm volatile("red.global.add.v4.f32 [%0], {%1, %2, %3, %4};"
                 :: "l"(p), "f"(v.x), "f"(v.y), "f"(v.z), "f"(v.w)
                 : "memory");
    if (lane == 0) atomicAdd(&g_cnt[g], 1.0f);
}

__global__ void div_kernel(float* __restrict__ out) {
    int i = blockIdx.x * blockDim.x + threadIdx.x;
    if (i >= N_GRAPHS * 32) return;
    int g = i >> 5;
    float c = fmaxf(g_cnt[g], 1.0f);
    float inv = 1.0f / c;
    float4 v = ((float4*)out)[i];
    v.x *= inv; v.y *= inv; v.z *= inv; v.w *= inv;
    ((float4*)out)[i] = v;
}

// ---------------------------------------------------------------------------
extern "C" void kernel_launch(void* const* d_in, const int* in_sizes, int n_in,
                              void* d_out, int out_size) {
    const int*   tok   = (const int*)d_in[0];
    const int*   ei    = (const int*)d_in[1];   // [2, N_EDGES]
    const int*   batch = (const int*)d_in[2];
    const float* emb   = (const float*)d_in[3];
    const float* W1    = (const float*)d_in[4];
    const float* b1    = (const float*)d_in[5];
    const float* W2    = (const float*)d_in[6];
    const float* b2    = (const float*)d_in[7];
    float* out = (float*)d_out;

    const int GEMM_SMEM = (128 * 128 + 64 * SA_STRIDE) * 4;   // 99328 B
    cudaFuncSetAttribute(gemm_kernel,
                         cudaFuncAttributeMaxDynamicSharedMemorySize, GEMM_SMEM);

    float *x, *agg, *h, *cnt;
    cudaGetSymbolAddress((void**)&x,   g_x);
    cudaGetSymbolAddress((void**)&agg, g_agg);
    cudaGetSymbolAddress((void**)&h,   g_h);
    cudaGetSymbolAddress((void**)&cnt, g_cnt);

    const int* src = ei;
    const int* dst = ei + N_EDGES;

    embed_kernel<<<(N_NODES * 32 + 255) / 256, 256>>>(tok, emb, x);

    int gemm_grid = (N_NODES + 127) / 128;    // 782

    for (int l = 0; l < LAYERS; l++) {
        zero_kernel<<<(N_NODES * 32 + 255) / 256, 256>>>((float4*)agg, N_NODES * 32);
        scatter_kernel<<<(N_EDGES * 32 + 255) / 256, 256>>>(x, src, dst, agg);
        // h = relu((x + agg) @ W1[l] + b1[l])
        gemm_kernel<<<gemm_grid, 256, GEMM_SMEM>>>(
            x, agg, W1 + (size_t)l * HID * HID, b1 + (size_t)l * HID, h);
        // x = relu(h @ W2[l] + b2[l])
        gemm_kernel<<<gemm_grid, 256, GEMM_SMEM>>>(
            h, nullptr, W2 + (size_t)l * HID * HID, b2 + (size_t)l * HID, x);
    }

    zero_kernel<<<(N_GRAPHS * 32 + 255) / 256, 256>>>((float4*)out, N_GRAPHS * 32);
    zero_kernel<<<(N_GRAPHS / 4 + 255) / 256, 256>>>((float4*)cnt, N_GRAPHS / 4);
    pool_kernel<<<(N_NODES * 32 + 255) / 256, 256>>>(x, batch, out);
    div_kernel<<<(N_GRAPHS * 32 + 255) / 256, 256>>>(out);
}

// round 11
// speedup vs baseline: 1.7532x; 1.6890x over previous
#include <cuda_runtime.h>
#include <cuda_bf16.h>
#include <cstdint>

#define N_NODES 100000
#define N_EDGES 600000
#define N_GRAPHS 2000
#define HID 128
#define LAYERS 6

// Scratch buffers (allocation-free rule: __device__ globals)
__device__ float g_x[(size_t)N_NODES * HID];
__device__ float g_agg[(size_t)N_NODES * HID];
__device__ float g_h[(size_t)N_NODES * HID];
__device__ float g_cnt[N_GRAPHS];
// Pre-converted W in fragment-ready bf16 hi/lo layout: [12 mats][8192 u32]
__device__ uint32_t g_whi[12 * 8192];
__device__ uint32_t g_wlo[12 * 8192];

// pack two floats into bf16x2: low half = e0, high half = e1
static __device__ __forceinline__ uint32_t pack_bf16x2(float e0, float e1) {
    uint32_t r;
    asm("cvt.rn.bf16x2.f32 %0, %1, %2;" : "=r"(r) : "f"(e1), "f"(e0));
    return r;
}

#define MMA_BF16(d, a, b)                                                     \
    asm volatile(                                                             \
        "mma.sync.aligned.m16n8k16.row.col.f32.bf16.bf16.f32 "                \
        "{%0,%1,%2,%3}, {%4,%5,%6,%7}, {%8,%9}, {%0,%1,%2,%3};"               \
        : "+f"((d)[0]), "+f"((d)[1]), "+f"((d)[2]), "+f"((d)[3])              \
        : "r"((a).x), "r"((a).y), "r"((a).z), "r"((a).w),                     \
          "r"((b).x), "r"((b).y))

// ---------------------------------------------------------------------------
// W pre-conversion: fp32 [128k x 128n] -> fragment-ready bf16 hi/lo.
// Tile (kt, nt) of m16n8k16 B-fragment: flat tile = kt*16 + nt, 64 u32/tile.
// u32 index w in tile: lane = w/2, reg = w%2;
//   k = kt*16 + reg*8 + (lane%4)*2 (+0/+1 in halves), n = nt*8 + lane/4.
// ---------------------------------------------------------------------------
__global__ void wconv_kernel(const float* __restrict__ W1,
                             const float* __restrict__ W2) {
    int mat = blockIdx.x;            // l*2 + s
    int l = mat >> 1, s = mat & 1;
    const float* W = (s ? W2 : W1) + (size_t)l * HID * HID;
    for (int i = threadIdx.x; i < 8192; i += 256) {
        int tile = i >> 6;
        int w    = i & 63;
        int lane = w >> 1, reg = w & 1;
        int kt = tile >> 4, nt = tile & 15;
        int k = kt * 16 + reg * 8 + (lane & 3) * 2;
        int n = nt * 8 + (lane >> 2);
        float x0 = W[k * HID + n];
        float x1 = W[(k + 1) * HID + n];
        uint32_t hp = pack_bf16x2(x0, x1);
        float h0 = __uint_as_float(hp << 16);
        float h1 = __uint_as_float(hp & 0xffff0000u);
        uint32_t lp = pack_bf16x2(x0 - h0, x1 - h1);
        g_whi[mat * 8192 + i] = hp;
        g_wlo[mat * 8192 + i] = lp;
    }
}

// ---------------------------------------------------------------------------
// Embedding gather
// ---------------------------------------------------------------------------
__global__ void embed_kernel(const int* __restrict__ tok,
                             const float* __restrict__ emb,
                             float* __restrict__ x) {
    int i = blockIdx.x * blockDim.x + threadIdx.x;
    if (i >= N_NODES * 32) return;
    int node = i >> 5;
    int c    = i & 31;
    int t = __ldg(tok + node);
    ((float4*)x)[(size_t)node * 32 + c] =
        ((const float4*)emb)[(size_t)t * 32 + c];
}

__global__ void zero_kernel(float4* __restrict__ p, int n4) {
    int i = blockIdx.x * blockDim.x + threadIdx.x;
    if (i < n4) p[i] = make_float4(0.f, 0.f, 0.f, 0.f);
}

// ---------------------------------------------------------------------------
// Edge scatter: agg[dst] += x[src]  (one warp per edge, vector RED)
// ---------------------------------------------------------------------------
__global__ void scatter_kernel(const float* __restrict__ x,
                               const int* __restrict__ src,
                               const int* __restrict__ dst,
                               float* __restrict__ agg) {
    int w = (blockIdx.x * blockDim.x + threadIdx.x) >> 5;
    if (w >= N_EDGES) return;
    int lane = threadIdx.x & 31;
    int s = __ldg(src + w);
    int d = __ldg(dst + w);
    float4 v = ((const float4*)x)[(size_t)s * 32 + lane];
    float* p = agg + (size_t)d * HID + lane * 4;
    asm volatile("red.global.add.v4.f32 [%0], {%1, %2, %3, %4};"
                 :: "l"(p), "f"(v.x), "f"(v.y), "f"(v.z), "f"(v.w)
                 : "memory");
}

// ---------------------------------------------------------------------------
// HMMA bf16 split GEMM: C = relu((A [+ A2]) @ W + b)
// CTA 256 threads (8 warps), tile M=128, N=128, K in 2 chunks of 64.
// Warp (wm, wn): m-tiles {2wm, 2wm+1} (16 rows each), n-tiles wn*8..+7.
// A staged fragment-ready in smem (one LDS.128 per m16k16 frag per lane).
// B fragments LDG.64 direct from pre-converted global (L2-hot).
// 3-pass split per tile: Ahi*Bhi + Ahi*Blo + Alo*Bhi.
// ---------------------------------------------------------------------------
__global__ __launch_bounds__(256, 2) void gemm_mma_kernel(
    const float* __restrict__ A, const float* __restrict__ A2,
    const uint32_t* __restrict__ whi, const uint32_t* __restrict__ wlo,
    const float* __restrict__ bias, float* __restrict__ C) {
    __shared__ uint32_t sAh[4096];   // 16KB: A chunk hi, fragment layout
    __shared__ uint32_t sAl[4096];   // 16KB: A chunk lo

    int tid  = threadIdx.x;
    int lane = tid & 31;
    int wid  = tid >> 5;
    int wm = wid >> 1;               // 0..3
    int wn = wid & 1;                // 0..1
    int row0 = blockIdx.x * 128;

    float acc[2][8][4];
#pragma unroll
    for (int mt = 0; mt < 2; mt++)
#pragma unroll
        for (int j = 0; j < 8; j++)
#pragma unroll
            for (int c = 0; c < 4; c++) acc[mt][j][c] = 0.f;

    for (int ck = 0; ck < 2; ck++) {
        if (ck) __syncthreads();
        // Convert A chunk [128 rows x 64 k] -> fragment-ready smem.
        // i -> r = i>>4 (row), c4 = i&15 (float4 within chunk, k = c4*4)
#pragma unroll
        for (int it = 0; it < 8; it++) {
            int i  = tid + it * 256;
            int r  = i >> 4;
            int c4 = i & 15;
            int row = row0 + r;
            float4 v = make_float4(0.f, 0.f, 0.f, 0.f);
            if (row < N_NODES) {
                v = ((const float4*)A)[(size_t)row * 32 + ck * 16 + c4];
                if (A2) {
                    float4 u = ((const float4*)A2)[(size_t)row * 32 + ck * 16 + c4];
                    v.x += u.x; v.y += u.y; v.z += u.z; v.w += u.w;
                }
            }
            int kl    = c4 * 4;                       // k within chunk
            int lane0 = (r & 7) * 4 + ((kl & 7) >> 1);
            int reg   = ((r & 15) >> 3) + (((kl & 15) >> 3) << 1);
            int tile  = ((kl >> 4) << 3) + (r >> 4);  // k-tile*8 + m-tile
            int base  = tile * 128 + reg;
            uint32_t hp0 = pack_bf16x2(v.x, v.y);
            uint32_t hp1 = pack_bf16x2(v.z, v.w);
            float h0 = __uint_as_float(hp0 << 16);
            float h1 = __uint_as_float(hp0 & 0xffff0000u);
            float h2 = __uint_as_float(hp1 << 16);
            float h3 = __uint_as_float(hp1 & 0xffff0000u);
            uint32_t lp0 = pack_bf16x2(v.x - h0, v.y - h1);
            uint32_t lp1 = pack_bf16x2(v.z - h2, v.w - h3);
            sAh[base + lane0 * 4]       = hp0;
            sAl[base + lane0 * 4]       = lp0;
            sAh[base + (lane0 + 1) * 4] = hp1;
            sAl[base + (lane0 + 1) * 4] = lp1;
        }
        __syncthreads();

#pragma unroll
        for (int kt = 0; kt < 4; kt++) {
            uint4 ah[2], al[2];
#pragma unroll
            for (int mt = 0; mt < 2; mt++) {
                int tile = kt * 8 + wm * 2 + mt;
                ah[mt] = *(const uint4*)&sAh[tile * 128 + lane * 4];
                al[mt] = *(const uint4*)&sAl[tile * 128 + lane * 4];
            }
            int ktg = ck * 4 + kt;                   // global k-tile 0..7
#pragma unroll
            for (int j = 0; j < 8; j++) {
                int tile = ktg * 16 + wn * 8 + j;
                uint2 bh = *(const uint2*)&whi[tile * 64 + lane * 2];
                uint2 bl = *(const uint2*)&wlo[tile * 64 + lane * 2];
#pragma unroll
                for (int mt = 0; mt < 2; mt++) {
                    MMA_BF16(acc[mt][j], ah[mt], bh);
                    MMA_BF16(acc[mt][j], ah[mt], bl);
                    MMA_BF16(acc[mt][j], al[mt], bh);
                }
            }
        }
    }

    // Epilogue: bias + relu, float2 stores
    int r_in = lane >> 2;
    int c2   = (lane & 3) * 2;
#pragma unroll
    for (int mt = 0; mt < 2; mt++) {
        int rb = row0 + (wm * 2 + mt) * 16 + r_in;
#pragma unroll
        for (int j = 0; j < 8; j++) {
            int col = (wn * 8 + j) * 8 + c2;
            float2 bb = *(const float2*)(bias + col);
            if (rb < N_NODES) {
                float2 o;
                o.x = fmaxf(acc[mt][j][0] + bb.x, 0.f);
                o.y = fmaxf(acc[mt][j][1] + bb.y, 0.f);
                *(float2*)(C + (size_t)rb * HID + col) = o;
            }
            if (rb + 8 < N_NODES) {
                float2 o;
                o.x = fmaxf(acc[mt][j][2] + bb.x, 0.f);
                o.y = fmaxf(acc[mt][j][3] + bb.y, 0.f);
                *(float2*)(C + (size_t)(rb + 8) * HID + col) = o;
            }
        }
    }
}

// ---------------------------------------------------------------------------
// Global mean pool
// ---------------------------------------------------------------------------
__global__ void pool_kernel(const float* __restrict__ x,
                            const int* __restrict__ batch,
                            float* __restrict__ out) {
    int w = (blockIdx.x * blockDim.x + threadIdx.x) >> 5;
    if (w >= N_NODES) return;
    int lane = threadIdx.x & 31;
    int g = __ldg(batch + w);
    float4 v = ((const float4*)x)[(size_t)w * 32 + lane];
    float* p = out + (size_t)g * HID + lane * 4;
    asm volatile("red.global.add.v4.f32 [%0], {%1, %2, %3, %4};"
                 :: "l"(p), "f"(v.x), "f"(v.y), "f"(v.z), "f"(v.w)
                 : "memory");
    if (lane == 0) atomicAdd(&g_cnt[g], 1.0f);
}

__global__ void div_kernel(float* __restrict__ out) {
    int i = blockIdx.x * blockDim.x + threadIdx.x;
    if (i >= N_GRAPHS * 32) return;
    int g = i >> 5;
    float c = fmaxf(g_cnt[g], 1.0f);
    float inv = 1.0f / c;
    float4 v = ((float4*)out)[i];
    v.x *= inv; v.y *= inv; v.z *= inv; v.w *= inv;
    ((float4*)out)[i] = v;
}

// ---------------------------------------------------------------------------
extern "C" void kernel_launch(void* const* d_in, const int* in_sizes, int n_in,
                              void* d_out, int out_size) {
    const int*   tok   = (const int*)d_in[0];
    const int*   ei    = (const int*)d_in[1];   // [2, N_EDGES]
    const int*   batch = (const int*)d_in[2];
    const float* emb   = (const float*)d_in[3];
    const float* W1    = (const float*)d_in[4];
    const float* b1    = (const float*)d_in[5];
    const float* W2    = (const float*)d_in[6];
    const float* b2    = (const float*)d_in[7];
    float* out = (float*)d_out;

    float *x, *agg, *h, *cnt;
    uint32_t *whi, *wlo;
    cudaGetSymbolAddress((void**)&x,   g_x);
    cudaGetSymbolAddress((void**)&agg, g_agg);
    cudaGetSymbolAddress((void**)&h,   g_h);
    cudaGetSymbolAddress((void**)&cnt, g_cnt);
    cudaGetSymbolAddress((void**)&whi, g_whi);
    cudaGetSymbolAddress((void**)&wlo, g_wlo);

    const int* src = ei;
    const int* dst = ei + N_EDGES;

    // Pre-convert all 12 weight matrices to fragment-ready bf16 hi/lo
    wconv_kernel<<<12, 256>>>(W1, W2);

    embed_kernel<<<(N_NODES * 32 + 255) / 256, 256>>>(tok, emb, x);

    int gemm_grid = (N_NODES + 127) / 128;    // 782

    for (int l = 0; l < LAYERS; l++) {
        zero_kernel<<<(N_NODES * 32 + 255) / 256, 256>>>((float4*)agg, N_NODES * 32);
        scatter_kernel<<<(N_EDGES * 32 + 255) / 256, 256>>>(x, src, dst, agg);
        // h = relu((x + agg) @ W1[l] + b1[l])
        gemm_mma_kernel<<<gemm_grid, 256>>>(
            x, agg, whi + (size_t)(l * 2 + 0) * 8192, wlo + (size_t)(l * 2 + 0) * 8192,
            b1 + (size_t)l * HID, h);
        // x = relu(h @ W2[l] + b2[l])
        gemm_mma_kernel<<<gemm_grid, 256>>>(
            h, nullptr, whi + (size_t)(l * 2 + 1) * 8192, wlo + (size_t)(l * 2 + 1) * 8192,
            b2 + (size_t)l * HID, x);
    }

    zero_kernel<<<(N_GRAPHS * 32 + 255) / 256, 256>>>((float4*)out, N_GRAPHS * 32);
    zero_kernel<<<(N_GRAPHS / 4 + 255) / 256, 256>>>((float4*)cnt, N_GRAPHS / 4);
    pool_kernel<<<(N_NODES * 32 + 255) / 256, 256>>>(x, batch, out);
    div_kernel<<<(N_GRAPHS * 32 + 255) / 256, 256>>>(out);
}

// round 12
// speedup vs baseline: 2.7862x; 1.5892x over previous
#include <cuda_runtime.h>
#include <cuda_bf16.h>
#include <cstdint>

#define N_NODES 100000
#define N_EDGES 600000
#define N_GRAPHS 2000
#define HID 128
#define LAYERS 6
#define SCAN_BLOCKS 98   // ceil(100000/1024)

// Scratch buffers (allocation-free rule: __device__ globals)
__device__ float g_x[(size_t)N_NODES * HID];
__device__ float g_xin[(size_t)N_NODES * HID];
__device__ float g_cnt[N_GRAPHS];
// CSR scratch
__device__ int g_deg[N_NODES];
__device__ int g_rpp[N_NODES];
__device__ int g_bsum[128];
__device__ int g_rowptr[N_NODES + 1];
__device__ int g_cursor[N_NODES];
__device__ int g_csr[N_EDGES];
// Pre-converted W in fragment-ready bf16 hi/lo layout: [12 mats][8192 u32]
__device__ uint32_t g_whi[12 * 8192];
__device__ uint32_t g_wlo[12 * 8192];

// pack two floats into bf16x2: low half = e0, high half = e1
static __device__ __forceinline__ uint32_t pack_bf16x2(float e0, float e1) {
    uint32_t r;
    asm("cvt.rn.bf16x2.f32 %0, %1, %2;" : "=r"(r) : "f"(e1), "f"(e0));
    return r;
}

#define MMA_BF16(d, a, b)                                                     \
    asm volatile(                                                             \
        "mma.sync.aligned.m16n8k16.row.col.f32.bf16.bf16.f32 "                \
        "{%0,%1,%2,%3}, {%4,%5,%6,%7}, {%8,%9}, {%0,%1,%2,%3};"               \
        : "+f"((d)[0]), "+f"((d)[1]), "+f"((d)[2]), "+f"((d)[3])              \
        : "r"((a).x), "r"((a).y), "r"((a).z), "r"((a).w),                     \
          "r"((b).x), "r"((b).y))

// ---------------------------------------------------------------------------
// W pre-conversion: fp32 [128k x 128n] -> fragment-ready bf16 hi/lo.
// ---------------------------------------------------------------------------
__global__ void wconv_kernel(const float* __restrict__ W1,
                             const float* __restrict__ W2) {
    int mat = blockIdx.x;            // l*2 + s
    int l = mat >> 1, s = mat & 1;
    const float* W = (s ? W2 : W1) + (size_t)l * HID * HID;
    for (int i = threadIdx.x; i < 8192; i += 256) {
        int tile = i >> 6;
        int w    = i & 63;
        int lane = w >> 1, reg = w & 1;
        int kt = tile >> 4, nt = tile & 15;
        int k = kt * 16 + reg * 8 + (lane & 3) * 2;
        int n = nt * 8 + (lane >> 2);
        float x0 = W[k * HID + n];
        float x1 = W[(k + 1) * HID + n];
        uint32_t hp = pack_bf16x2(x0, x1);
        float h0 = __uint_as_float(hp << 16);
        float h1 = __uint_as_float(hp & 0xffff0000u);
        uint32_t lp = pack_bf16x2(x0 - h0, x1 - h1);
        g_whi[mat * 8192 + i] = hp;
        g_wlo[mat * 8192 + i] = lp;
    }
}

// ---------------------------------------------------------------------------
// CSR build: degree histogram -> 3-kernel exclusive scan -> slot fill
// ---------------------------------------------------------------------------
__global__ void deg_kernel(const int* __restrict__ dst) {
    int e = blockIdx.x * blockDim.x + threadIdx.x;
    if (e < N_EDGES) atomicAdd(&g_deg[__ldg(dst + e)], 1);
}

__global__ void scan1_kernel() {
    __shared__ int s[1024];
    int t = threadIdx.x, b = blockIdx.x;
    int idx = b * 1024 + t;
    int v = (idx < N_NODES) ? g_deg[idx] : 0;
    s[t] = v;
    __syncthreads();
#pragma unroll
    for (int off = 1; off < 1024; off <<= 1) {
        int u = (t >= off) ? s[t - off] : 0;
        __syncthreads();
        s[t] += u;
        __syncthreads();
    }
    if (idx < N_NODES) g_rpp[idx] = s[t] - v;    // exclusive within block
    if (t == 1023) g_bsum[b] = s[1023];
}

__global__ void scan2_kernel() {   // 1 block, 128 threads
    __shared__ int s[128];
    int t = threadIdx.x;
    int v = (t < SCAN_BLOCKS) ? g_bsum[t] : 0;
    s[t] = v;
    __syncthreads();
#pragma unroll
    for (int off = 1; off < 128; off <<= 1) {
        int u = (t >= off) ? s[t - off] : 0;
        __syncthreads();
        s[t] += u;
        __syncthreads();
    }
    if (t < SCAN_BLOCKS) g_bsum[t] = s[t] - v;   // exclusive
    if (t == 127) g_rowptr[N_NODES] = s[127];    // total (= N_EDGES)
}

__global__ void scan3_kernel() {
    int idx = blockIdx.x * blockDim.x + threadIdx.x;
    if (idx >= N_NODES) return;
    int r = g_rpp[idx] + g_bsum[idx >> 10];
    g_rowptr[idx] = r;
    g_cursor[idx] = r;
}

__global__ void fill_kernel(const int* __restrict__ src,
                            const int* __restrict__ dst) {
    int e = blockIdx.x * blockDim.x + threadIdx.x;
    if (e >= N_EDGES) return;
    int slot = atomicAdd(&g_cursor[__ldg(dst + e)], 1);
    g_csr[slot] = __ldg(src + e);
}

// ---------------------------------------------------------------------------
// Embedding gather
// ---------------------------------------------------------------------------
__global__ void embed_kernel(const int* __restrict__ tok,
                             const float* __restrict__ emb,
                             float* __restrict__ x) {
    int i = blockIdx.x * blockDim.x + threadIdx.x;
    if (i >= N_NODES * 32) return;
    int node = i >> 5;
    int c    = i & 31;
    int t = __ldg(tok + node);
    ((float4*)x)[(size_t)node * 32 + c] =
        ((const float4*)emb)[(size_t)t * 32 + c];
}

__global__ void zero_kernel(float4* __restrict__ p, int n4) {
    int i = blockIdx.x * blockDim.x + threadIdx.x;
    if (i < n4) p[i] = make_float4(0.f, 0.f, 0.f, 0.f);
}

// ---------------------------------------------------------------------------
// CSR gather-sum: xin[v] = x[v] + sum_{src in N(v)} x[src]
// One warp per node; lane owns one float4 (4 consecutive channels).
// ---------------------------------------------------------------------------
__global__ void gather_kernel(const float* __restrict__ x,
                              float* __restrict__ xin) {
    int node = (blockIdx.x * blockDim.x + threadIdx.x) >> 5;
    if (node >= N_NODES) return;
    int lane = threadIdx.x & 31;
    int beg = __ldg(&g_rowptr[node]);
    int end = __ldg(&g_rowptr[node + 1]);
    float4 s = ((const float4*)x)[(size_t)node * 32 + lane];
    int e = beg;
    for (; e + 1 < end; e += 2) {
        int s0 = __ldg(&g_csr[e]);
        int s1 = __ldg(&g_csr[e + 1]);
        float4 v0 = ((const float4*)x)[(size_t)s0 * 32 + lane];
        float4 v1 = ((const float4*)x)[(size_t)s1 * 32 + lane];
        s.x += v0.x + v1.x; s.y += v0.y + v1.y;
        s.z += v0.z + v1.z; s.w += v0.w + v1.w;
    }
    if (e < end) {
        int s0 = __ldg(&g_csr[e]);
        float4 v0 = ((const float4*)x)[(size_t)s0 * 32 + lane];
        s.x += v0.x; s.y += v0.y; s.z += v0.z; s.w += v0.w;
    }
    ((float4*)xin)[(size_t)node * 32 + lane] = s;
}

// ---------------------------------------------------------------------------
// Fused double-GEMM layer: xout = relu(relu(xin@W1+b1)@W2+b2)
// CTA 256 threads (8 warps), tile M=128, N=128.
// Warp (wm, wn): m-tiles {2wm,2wm+1}, n-tiles wn*8..+7.
// Stage 1: xin -> frag smem (hi/lo, both 64-k chunks) -> acc vs W1 frags.
// Epilogue1 writes relu(h+b1) straight back into frag smem (hi/lo).
// Stage 2: same compute vs W2 frags -> relu(+b2) -> global store.
// 3-pass bf16 split per MMA tile. Dynamic smem 64KB -> 2 CTAs/SM.
// ---------------------------------------------------------------------------
__global__ __launch_bounds__(256, 2) void layer_kernel(
    const float* __restrict__ xin,
    const uint32_t* __restrict__ w1h, const uint32_t* __restrict__ w1l,
    const float* __restrict__ b1,
    const uint32_t* __restrict__ w2h, const uint32_t* __restrict__ w2l,
    const float* __restrict__ b2,
    float* __restrict__ xout) {
    extern __shared__ uint32_t smu[];
    uint32_t* sAh = smu;            // [2][4096] hi frags (2 k-chunks)
    uint32_t* sAl = smu + 8192;     // [2][4096] lo frags

    int tid  = threadIdx.x;
    int lane = tid & 31;
    int wid  = tid >> 5;
    int wm = wid >> 1;               // 0..3
    int wn = wid & 1;                // 0..1
    int row0 = blockIdx.x * 128;

    // ---- Stage-1 A load: 128 rows x 128 k -> frag smem (both chunks) ----
#pragma unroll
    for (int it = 0; it < 16; it++) {
        int i  = tid + it * 256;     // 0..4095 float4
        int r  = i >> 5;
        int c4 = i & 31;
        int row = row0 + r;
        float4 v = make_float4(0.f, 0.f, 0.f, 0.f);
        if (row < N_NODES)
            v = ((const float4*)xin)[(size_t)row * 32 + c4];
        int ck = c4 >> 4;
        int kk = (c4 & 15) * 4;      // k within chunk
        int lane0 = (r & 7) * 4 + ((kk & 7) >> 1);
        int reg   = ((r & 15) >> 3) + (((kk & 15) >> 3) << 1);
        int tile  = ((kk >> 4) << 3) + (r >> 4);
        int base  = ck * 4096 + tile * 128 + reg;
        uint32_t hp0 = pack_bf16x2(v.x, v.y);
        uint32_t hp1 = pack_bf16x2(v.z, v.w);
        float h0 = __uint_as_float(hp0 << 16);
        float h1 = __uint_as_float(hp0 & 0xffff0000u);
        float h2 = __uint_as_float(hp1 << 16);
        float h3 = __uint_as_float(hp1 & 0xffff0000u);
        sAh[base + lane0 * 4]       = hp0;
        sAl[base + lane0 * 4]       = pack_bf16x2(v.x - h0, v.y - h1);
        sAh[base + (lane0 + 1) * 4] = hp1;
        sAl[base + (lane0 + 1) * 4] = pack_bf16x2(v.z - h2, v.w - h3);
    }
    __syncthreads();

    float acc[2][8][4];
#pragma unroll
    for (int mt = 0; mt < 2; mt++)
#pragma unroll
        for (int j = 0; j < 8; j++)
#pragma unroll
            for (int c = 0; c < 4; c++) acc[mt][j][c] = 0.f;

    // ---- Stage-1 compute: (xin) @ W1 ----
#pragma unroll
    for (int ktg = 0; ktg < 8; ktg++) {
        int ck = ktg >> 2, kt = ktg & 3;
        uint4 ah[2], al[2];
#pragma unroll
        for (int mt = 0; mt < 2; mt++) {
            int tile = ck * 4096 + (kt * 8 + wm * 2 + mt) * 128;
            ah[mt] = *(const uint4*)&sAh[tile + lane * 4];
            al[mt] = *(const uint4*)&sAl[tile + lane * 4];
        }
#pragma unroll
        for (int j = 0; j < 8; j++) {
            int tile = ktg * 16 + wn * 8 + j;
            uint2 bh = *(const uint2*)&w1h[tile * 64 + lane * 2];
            uint2 bl = *(const uint2*)&w1l[tile * 64 + lane * 2];
#pragma unroll
            for (int mt = 0; mt < 2; mt++) {
                MMA_BF16(acc[mt][j], ah[mt], bh);
                MMA_BF16(acc[mt][j], ah[mt], bl);
                MMA_BF16(acc[mt][j], al[mt], bh);
            }
        }
    }
    __syncthreads();   // frag smem fully consumed; safe to overwrite

    // ---- Epilogue 1: h = relu(acc + b1) -> frag smem (hi/lo) ----
#pragma unroll
    for (int mt = 0; mt < 2; mt++) {
        int rb = (wm * 2 + mt) * 16 + (lane >> 2);   // local row (<8 within tile)
#pragma unroll
        for (int j = 0; j < 8; j++) {
            int col = (wn * 8 + j) * 8 + (lane & 3) * 2;
            float2 bb = *(const float2*)(b1 + col);
            float h00 = fmaxf(acc[mt][j][0] + bb.x, 0.f);
            float h01 = fmaxf(acc[mt][j][1] + bb.y, 0.f);
            float h10 = fmaxf(acc[mt][j][2] + bb.x, 0.f);
            float h11 = fmaxf(acc[mt][j][3] + bb.y, 0.f);
            int ck2 = col >> 6;
            int kl  = col & 63;
            int lane0 = (rb & 7) * 4 + ((kl & 7) >> 1);
            int reg   = (((kl & 15) >> 3) << 1);     // rb&15 < 8 -> row bit 0
            int tile  = ((kl >> 4) << 3) + (rb >> 4);
            int idx0  = ck2 * 4096 + tile * 128 + reg + lane0 * 4;
            uint32_t hp0 = pack_bf16x2(h00, h01);
            float e0 = __uint_as_float(hp0 << 16);
            float e1 = __uint_as_float(hp0 & 0xffff0000u);
            sAh[idx0] = hp0;
            sAl[idx0] = pack_bf16x2(h00 - e0, h01 - e1);
            uint32_t hp1 = pack_bf16x2(h10, h11);     // row rb+8 -> reg+1
            float e2 = __uint_as_float(hp1 << 16);
            float e3 = __uint_as_float(hp1 & 0xffff0000u);
            sAh[idx0 + 1] = hp1;
            sAl[idx0 + 1] = pack_bf16x2(h10 - e2, h11 - e3);
        }
    }
    __syncthreads();

    // ---- Stage-2 compute: h @ W2 ----
#pragma unroll
    for (int mt = 0; mt < 2; mt++)
#pragma unroll
        for (int j = 0; j < 8; j++)
#pragma unroll
            for (int c = 0; c < 4; c++) acc[mt][j][c] = 0.f;

#pragma unroll
    for (int ktg = 0; ktg < 8; ktg++) {
        int ck = ktg >> 2, kt = ktg & 3;
        uint4 ah[2], al[2];
#pragma unroll
        for (int mt = 0; mt < 2; mt++) {
            int tile = ck * 4096 + (kt * 8 + wm * 2 + mt) * 128;
            ah[mt] = *(const uint4*)&sAh[tile + lane * 4];
            al[mt] = *(const uint4*)&sAl[tile + lane * 4];
        }
#pragma unroll
        for (int j = 0; j < 8; j++) {
            int tile = ktg * 16 + wn * 8 + j;
            uint2 bh = *(const uint2*)&w2h[tile * 64 + lane * 2];
            uint2 bl = *(const uint2*)&w2l[tile * 64 + lane * 2];
#pragma unroll
            for (int mt = 0; mt < 2; mt++) {
                MMA_BF16(acc[mt][j], ah[mt], bh);
                MMA_BF16(acc[mt][j], ah[mt], bl);
                MMA_BF16(acc[mt][j], al[mt], bh);
            }
        }
    }

    // ---- Epilogue 2: xout = relu(acc + b2), float2 stores ----
    int r_in = lane >> 2;
    int c2   = (lane & 3) * 2;
#pragma unroll
    for (int mt = 0; mt < 2; mt++) {
        int rb = row0 + (wm * 2 + mt) * 16 + r_in;
#pragma unroll
        for (int j = 0; j < 8; j++) {
            int col = (wn * 8 + j) * 8 + c2;
            float2 bb = *(const float2*)(b2 + col);
            if (rb < N_NODES) {
                float2 o;
                o.x = fmaxf(acc[mt][j][0] + bb.x, 0.f);
                o.y = fmaxf(acc[mt][j][1] + bb.y, 0.f);
                *(float2*)(xout + (size_t)rb * HID + col) = o;
            }
            if (rb + 8 < N_NODES) {
                float2 o;
                o.x = fmaxf(acc[mt][j][2] + bb.x, 0.f);
                o.y = fmaxf(acc[mt][j][3] + bb.y, 0.f);
                *(float2*)(xout + (size_t)(rb + 8) * HID + col) = o;
            }
        }
    }
}

// ---------------------------------------------------------------------------
// Global mean pool
// ---------------------------------------------------------------------------
__global__ void pool_kernel(const float* __restrict__ x,
                            const int* __restrict__ batch,
                            float* __restrict__ out) {
    int w = (blockIdx.x * blockDim.x + threadIdx.x) >> 5;
    if (w >= N_NODES) return;
    int lane = threadIdx.x & 31;
    int g = __ldg(batch + w);
    float4 v = ((const float4*)x)[(size_t)w * 32 + lane];
    float* p = out + (size_t)g * HID + lane * 4;
    asm volatile("red.global.add.v4.f32 [%0], {%1, %2, %3, %4};"
                 :: "l"(p), "f"(v.x), "f"(v.y), "f"(v.z), "f"(v.w)
                 : "memory");
    if (lane == 0) atomicAdd(&g_cnt[g], 1.0f);
}

__global__ void div_kernel(float* __restrict__ out) {
    int i = blockIdx.x * blockDim.x + threadIdx.x;
    if (i >= N_GRAPHS * 32) return;
    int g = i >> 5;
    float c = fmaxf(g_cnt[g], 1.0f);
    float inv = 1.0f / c;
    float4 v = ((float4*)out)[i];
    v.x *= inv; v.y *= inv; v.z *= inv; v.w *= inv;
    ((float4*)out)[i] = v;
}

// ---------------------------------------------------------------------------
extern "C" void kernel_launch(void* const* d_in, const int* in_sizes, int n_in,
                              void* d_out, int out_size) {
    const int*   tok   = (const int*)d_in[0];
    const int*   ei    = (const int*)d_in[1];   // [2, N_EDGES]
    const int*   batch = (const int*)d_in[2];
    const float* emb   = (const float*)d_in[3];
    const float* W1    = (const float*)d_in[4];
    const float* b1    = (const float*)d_in[5];
    const float* W2    = (const float*)d_in[6];
    const float* b2    = (const float*)d_in[7];
    float* out = (float*)d_out;

    const int LAYER_SMEM = 16384 * 4;   // 64KB dynamic
    cudaFuncSetAttribute(layer_kernel,
                         cudaFuncAttributeMaxDynamicSharedMemorySize, LAYER_SMEM);

    float *x, *xin, *cnt;
    int *deg;
    uint32_t *whi, *wlo;
    cudaGetSymbolAddress((void**)&x,   g_x);
    cudaGetSymbolAddress((void**)&xin, g_xin);
    cudaGetSymbolAddress((void**)&cnt, g_cnt);
    cudaGetSymbolAddress((void**)&deg, g_deg);
    cudaGetSymbolAddress((void**)&whi, g_whi);
    cudaGetSymbolAddress((void**)&wlo, g_wlo);

    const int* src = ei;
    const int* dst = ei + N_EDGES;

    // Pre-convert weights to fragment-ready bf16 hi/lo
    wconv_kernel<<<12, 256>>>(W1, W2);

    // Build CSR (edge list is constant within the launch)
    zero_kernel<<<(N_NODES / 4 + 255) / 256, 256>>>((float4*)deg, N_NODES / 4);
    deg_kernel<<<(N_EDGES + 255) / 256, 256>>>(dst);
    scan1_kernel<<<SCAN_BLOCKS, 1024>>>();
    scan2_kernel<<<1, 128>>>();
    scan3_kernel<<<(N_NODES + 255) / 256, 256>>>();
    fill_kernel<<<(N_EDGES + 255) / 256, 256>>>(src, dst);

    // Embedding
    embed_kernel<<<(N_NODES * 32 + 255) / 256, 256>>>(tok, emb, x);

    int gemm_grid = (N_NODES + 127) / 128;    // 782

    for (int l = 0; l < LAYERS; l++) {
        gather_kernel<<<(N_NODES * 32 + 255) / 256, 256>>>(x, xin);
        layer_kernel<<<gemm_grid, 256, LAYER_SMEM>>>(
            xin,
            whi + (size_t)(l * 2 + 0) * 8192, wlo + (size_t)(l * 2 + 0) * 8192,
            b1 + (size_t)l * HID,
            whi + (size_t)(l * 2 + 1) * 8192, wlo + (size_t)(l * 2 + 1) * 8192,
            b2 + (size_t)l * HID,
            x);
    }

    // Mean pool
    zero_kernel<<<(N_GRAPHS * 32 + 255) / 256, 256>>>((float4*)out, N_GRAPHS * 32);
    zero_kernel<<<(N_GRAPHS / 4 + 255) / 256, 256>>>((float4*)cnt, N_GRAPHS / 4);
    pool_kernel<<<(N_NODES * 32 + 255) / 256, 256>>>(x, batch, out);
    div_kernel<<<(N_GRAPHS * 32 + 255) / 256, 256>>>(out);
}